// round 16
// baseline (speedup 1.0000x reference)
#include <cuda_runtime.h>
#include <cuda_bf16.h>
#include <cuda_fp16.h>
#include <cstdint>

// Problem constants
constexpr int V  = 32000;
constexpr int H  = 1024;
constexpr int B  = 64;
constexpr int T  = 1024;
constexpr int NC = 16;
constexpr int HID_OFF  = B * V;
constexpr int ATTN_OFF = HID_OFF + B * H;

// ---------------- scratch globals --------------------------------------------
__device__ float g_gx[B * 3 * H];
__device__ float g_gh[B * 3 * H];
__device__ float g_cat[B * 2 * H];
__device__ float g_scores[B * T];
__device__ float g_pm[B * NC];
__device__ float g_ps[B * NC];
__device__ float g_pc[B * NC * H];
__device__ float g_cop[B * H];

__device__ __nv_bfloat16 g_embhi[B * H];
__device__ __nv_bfloat16 g_emblo[B * H];
__device__ __nv_bfloat16 g_h0hi[B * H];
__device__ __nv_bfloat16 g_h0lo[B * H];
__device__ __nv_bfloat16 g_cathi[B * 2 * H];
__device__ __nv_bfloat16 g_catlo[B * 2 * H];
__device__ __half g_cof[B * H];             // fp16 X for the out GEMM

// ---------------- helpers ------------------------------------------------------
__device__ __forceinline__ uint32_t swz(uint32_t o) { return o ^ ((o >> 3) & 0x70); }
__device__ __forceinline__ uint32_t smem_u32(const void* p) {
    uint32_t a;
    asm("{ .reg .u64 t; cvta.to.shared.u64 t, %1; cvt.u32.u64 %0, t; }" : "=r"(a) : "l"(p));
    return a;
}
__device__ __forceinline__ void ldsm4(uint32_t& r0, uint32_t& r1, uint32_t& r2, uint32_t& r3,
                                      uint32_t addr) {
    asm volatile("ldmatrix.sync.aligned.m8n8.x4.shared.b16 {%0,%1,%2,%3}, [%4];"
                 : "=r"(r0), "=r"(r1), "=r"(r2), "=r"(r3) : "r"(addr));
}
__device__ __forceinline__ void mma16816(float* c, const uint32_t* a, uint32_t b0, uint32_t b1) {
    asm volatile(
        "mma.sync.aligned.m16n8k16.row.col.f32.bf16.bf16.f32 "
        "{%0,%1,%2,%3}, {%4,%5,%6,%7}, {%8,%9}, {%0,%1,%2,%3};"
        : "+f"(c[0]), "+f"(c[1]), "+f"(c[2]), "+f"(c[3])
        : "r"(a[0]), "r"(a[1]), "r"(a[2]), "r"(a[3]), "r"(b0), "r"(b1));
}
__device__ __forceinline__ void mma16816h(float* c, const uint32_t* a, uint32_t b0, uint32_t b1) {
    asm volatile(
        "mma.sync.aligned.m16n8k16.row.col.f32.f16.f16.f32 "
        "{%0,%1,%2,%3}, {%4,%5,%6,%7}, {%8,%9}, {%0,%1,%2,%3};"
        : "+f"(c[0]), "+f"(c[1]), "+f"(c[2]), "+f"(c[3])
        : "r"(a[0]), "r"(a[1]), "r"(a[2]), "r"(a[3]), "r"(b0), "r"(b1));
}
__device__ __forceinline__ uint32_t pk2(float first, float second) {
    uint32_t r;
    asm("cvt.rn.bf16x2.f32 %0, %2, %1;" : "=r"(r) : "f"(first), "f"(second));
    return r;
}
__device__ __forceinline__ uint32_t pkh(__nv_bfloat16 a, __nv_bfloat16 b) {
    return (uint32_t)__bfloat16_as_ushort(a) | ((uint32_t)__bfloat16_as_ushort(b) << 16);
}
__device__ __forceinline__ uint32_t pk2hf(float first, float second) {
    uint32_t r;
    asm("cvt.rn.f16x2.f32 %0, %2, %1;" : "=r"(r) : "f"(first), "f"(second));
    return r;
}

constexpr int OFF_WHI = 0;
constexpr int OFF_WLO = 16384;
constexpr int OFF_XHI = 32768;
constexpr int OFF_XLO = 40960;

// ---------------- split-bf16 3-term HMMA GEMM (GRU / cat), atomic epilogue -----
// Term-major MMA order: all-jj per term -> accumulator RAW distance = 8 MMAs.
__device__ __forceinline__ void gemm_bf16_3t(const float* __restrict__ W,
                                             const __nv_bfloat16* __restrict__ Xhi,
                                             const __nv_bfloat16* __restrict__ Xlo,
                                             float* __restrict__ Cf,
                                             int NOUT, int KDIM, int m0, int k0, int kLen) {
    __shared__ __align__(1024) uint8_t sm[49152];
    const int tid = threadIdx.x;
    const int lane = tid & 31, w = tid >> 5;
    const uint32_t sb = smem_u32(sm);

    const int wr0 = tid >> 4;
    const int wkq = tid & 15;
    const float* wp = W + (size_t)(m0 + wr0) * KDIM + k0 + wkq * 4;
    const size_t wstep = (size_t)16 * KDIM;

    const int xrow  = tid >> 2;
    const int xq    = tid & 3;
    const __nv_bfloat16* xhp = Xhi + (size_t)xrow * KDIM + k0 + xq * 16;
    const __nv_bfloat16* xlp = Xlo + (size_t)xrow * KDIM + k0 + xq * 16;

    const uint32_t a_row = (w << 4) + (lane & 15);
    const uint32_t a_chi = (lane >> 4) << 4;
    const uint32_t b_row8 = (lane & 7) | (((uint32_t)lane >> 4) << 3);
    const uint32_t b_chi  = (((uint32_t)lane >> 3) & 1) << 4;

    float acc[8][4];
#pragma unroll
    for (int j = 0; j < 8; ++j)
#pragma unroll
        for (int q = 0; q < 4; ++q) acc[j][q] = 0.f;

    float4 wreg[8];
    uint4  xr[4];
#pragma unroll
    for (int q = 0; q < 8; ++q) wreg[q] = *reinterpret_cast<const float4*>(wp + q * wstep);
    xr[0] = *reinterpret_cast<const uint4*>(xhp);
    xr[1] = *reinterpret_cast<const uint4*>(xhp + 8);
    xr[2] = *reinterpret_cast<const uint4*>(xlp);
    xr[3] = *reinterpret_cast<const uint4*>(xlp + 8);

    const int nch = kLen >> 6;
    for (int ch = 0; ch < nch; ++ch) {
#pragma unroll
        for (int q = 0; q < 8; ++q) {
            float4 f = wreg[q];
            __nv_bfloat16 b0 = __float2bfloat16_rn(f.x);
            __nv_bfloat16 b1 = __float2bfloat16_rn(f.y);
            __nv_bfloat16 b2 = __float2bfloat16_rn(f.z);
            __nv_bfloat16 b3 = __float2bfloat16_rn(f.w);
            uint2 hu = make_uint2(pkh(b0, b1), pkh(b2, b3));
            uint2 lu = make_uint2(pk2(f.x - __bfloat162float(b0), f.y - __bfloat162float(b1)),
                                  pk2(f.z - __bfloat162float(b2), f.w - __bfloat162float(b3)));
            uint32_t off = swz((uint32_t)((wr0 + 16 * q) * 128 + wkq * 8));
            *reinterpret_cast<uint2*>(sm + OFF_WHI + off) = hu;
            *reinterpret_cast<uint2*>(sm + OFF_WLO + off) = lu;
        }
        {
            uint32_t o0 = swz((uint32_t)(xrow * 128 + xq * 32));
            uint32_t o1 = swz((uint32_t)(xrow * 128 + xq * 32 + 16));
            *reinterpret_cast<uint4*>(sm + OFF_XHI + o0) = xr[0];
            *reinterpret_cast<uint4*>(sm + OFF_XHI + o1) = xr[1];
            *reinterpret_cast<uint4*>(sm + OFF_XLO + o0) = xr[2];
            *reinterpret_cast<uint4*>(sm + OFF_XLO + o1) = xr[3];
        }
        __syncthreads();

        if (ch + 1 < nch) {
            const int kc = (ch + 1) * 64;
#pragma unroll
            for (int q = 0; q < 8; ++q)
                wreg[q] = *reinterpret_cast<const float4*>(wp + kc + q * wstep);
            xr[0] = *reinterpret_cast<const uint4*>(xhp + kc);
            xr[1] = *reinterpret_cast<const uint4*>(xhp + kc + 8);
            xr[2] = *reinterpret_cast<const uint4*>(xlp + kc);
            xr[3] = *reinterpret_cast<const uint4*>(xlp + kc + 8);
        }

#pragma unroll
        for (int s = 0; s < 4; ++s) {
            uint32_t ah[4], al[4];
            uint32_t aoff = swz(a_row * 128 + s * 32 + a_chi);
            ldsm4(ah[0], ah[1], ah[2], ah[3], sb + OFF_WHI + aoff);
            ldsm4(al[0], al[1], al[2], al[3], sb + OFF_WLO + aoff);
            uint32_t bh[4][4], bl[4][4];
#pragma unroll
            for (int jj = 0; jj < 4; ++jj) {
                uint32_t boff = swz((16 * jj + b_row8) * 128 + s * 32 + b_chi);
                ldsm4(bh[jj][0], bh[jj][1], bh[jj][2], bh[jj][3], sb + OFF_XHI + boff);
                ldsm4(bl[jj][0], bl[jj][1], bl[jj][2], bl[jj][3], sb + OFF_XLO + boff);
            }
            // term 1: Whi * Xhi   (acc RAW distance = 8 MMAs)
#pragma unroll
            for (int jj = 0; jj < 4; ++jj) {
                mma16816(acc[2 * jj],     ah, bh[jj][0], bh[jj][1]);
                mma16816(acc[2 * jj + 1], ah, bh[jj][2], bh[jj][3]);
            }
            // term 2: Wlo * Xhi
#pragma unroll
            for (int jj = 0; jj < 4; ++jj) {
                mma16816(acc[2 * jj],     al, bh[jj][0], bh[jj][1]);
                mma16816(acc[2 * jj + 1], al, bh[jj][2], bh[jj][3]);
            }
            // term 3: Whi * Xlo
#pragma unroll
            for (int jj = 0; jj < 4; ++jj) {
                mma16816(acc[2 * jj],     ah, bl[jj][0], bl[jj][1]);
                mma16816(acc[2 * jj + 1], ah, bl[jj][2], bl[jj][3]);
            }
        }
        __syncthreads();
    }

    const int g = lane >> 2, t = lane & 3;
    const int m = m0 + w * 16 + g;
#pragma unroll
    for (int jj = 0; jj < 8; ++jj) {
        const int b0 = 8 * jj + 2 * t;
        atomicAdd(&Cf[(size_t)b0 * NOUT + m],           acc[jj][0]);
        atomicAdd(&Cf[(size_t)(b0 + 1) * NOUT + m],     acc[jj][1]);
        atomicAdd(&Cf[(size_t)b0 * NOUT + m + 8],       acc[jj][2]);
        atomicAdd(&Cf[(size_t)(b0 + 1) * NOUT + m + 8], acc[jj][3]);
    }
}

// ---------------- single-term fp16 HMMA GEMM (out projection) ------------------
constexpr int F1_WHI = 0;
constexpr int F1_X   = 16384;

__device__ __forceinline__ void gemm_f16_1t(const float* __restrict__ W,
                                            const __half* __restrict__ X,
                                            float* __restrict__ Cf,
                                            int NOUT, int KDIM, int m0, int k0, int kLen) {
    __shared__ __align__(1024) uint8_t sm[24576];
    const int tid = threadIdx.x;
    const int lane = tid & 31, w = tid >> 5;
    const uint32_t sb = smem_u32(sm);

    const int wr0 = tid >> 4;
    const int wkq = tid & 15;
    const float* wp = W + (size_t)(m0 + wr0) * KDIM + k0 + wkq * 4;
    const size_t wstep = (size_t)16 * KDIM;

    const int xrow  = tid >> 2;
    const int xq    = tid & 3;
    const __half* xp = X + (size_t)xrow * KDIM + k0 + xq * 16;

    const uint32_t a_row = (w << 4) + (lane & 15);
    const uint32_t a_chi = (lane >> 4) << 4;
    const uint32_t b_row8 = (lane & 7) | (((uint32_t)lane >> 4) << 3);
    const uint32_t b_chi  = (((uint32_t)lane >> 3) & 1) << 4;

    float acc[8][4];
#pragma unroll
    for (int j = 0; j < 8; ++j)
#pragma unroll
        for (int q = 0; q < 4; ++q) acc[j][q] = 0.f;

    float4 wreg[8];
    uint4  xr[2];
#pragma unroll
    for (int q = 0; q < 8; ++q) wreg[q] = *reinterpret_cast<const float4*>(wp + q * wstep);
    xr[0] = *reinterpret_cast<const uint4*>(xp);
    xr[1] = *reinterpret_cast<const uint4*>(xp + 8);

    const int nch = kLen >> 6;
    for (int ch = 0; ch < nch; ++ch) {
#pragma unroll
        for (int q = 0; q < 8; ++q) {
            float4 f = wreg[q];
            uint2 hu = make_uint2(pk2hf(f.x, f.y), pk2hf(f.z, f.w));
            uint32_t off = swz((uint32_t)((wr0 + 16 * q) * 128 + wkq * 8));
            *reinterpret_cast<uint2*>(sm + F1_WHI + off) = hu;
        }
        {
            uint32_t o0 = swz((uint32_t)(xrow * 128 + xq * 32));
            uint32_t o1 = swz((uint32_t)(xrow * 128 + xq * 32 + 16));
            *reinterpret_cast<uint4*>(sm + F1_X + o0) = xr[0];
            *reinterpret_cast<uint4*>(sm + F1_X + o1) = xr[1];
        }
        __syncthreads();

        if (ch + 1 < nch) {
            const int kc = (ch + 1) * 64;
#pragma unroll
            for (int q = 0; q < 8; ++q)
                wreg[q] = *reinterpret_cast<const float4*>(wp + kc + q * wstep);
            xr[0] = *reinterpret_cast<const uint4*>(xp + kc);
            xr[1] = *reinterpret_cast<const uint4*>(xp + kc + 8);
        }

#pragma unroll
        for (int s = 0; s < 4; ++s) {
            uint32_t ah[4];
            uint32_t aoff = swz(a_row * 128 + s * 32 + a_chi);
            ldsm4(ah[0], ah[1], ah[2], ah[3], sb + F1_WHI + aoff);
#pragma unroll
            for (int jj = 0; jj < 4; ++jj) {
                uint32_t boff = swz((16 * jj + b_row8) * 128 + s * 32 + b_chi);
                uint32_t bh[4];
                ldsm4(bh[0], bh[1], bh[2], bh[3], sb + F1_X + boff);
                mma16816h(acc[2 * jj],     ah, bh[0], bh[1]);
                mma16816h(acc[2 * jj + 1], ah, bh[2], bh[3]);
            }
        }
        __syncthreads();
    }

    const int g = lane >> 2, t = lane & 3;
    const int m = m0 + w * 16 + g;
#pragma unroll
    for (int jj = 0; jj < 8; ++jj) {
        const int b0 = 8 * jj + 2 * t;
        atomicAdd(&Cf[(size_t)b0 * NOUT + m],           acc[jj][0]);
        atomicAdd(&Cf[(size_t)(b0 + 1) * NOUT + m],     acc[jj][1]);
        atomicAdd(&Cf[(size_t)b0 * NOUT + m + 8],       acc[jj][2]);
        atomicAdd(&Cf[(size_t)(b0 + 1) * NOUT + m + 8], acc[jj][3]);
    }
}

__global__ void __launch_bounds__(256, 2) k_gemm_gru(const float* __restrict__ w_ih,
                                                     const float* __restrict__ w_hh) {
    const int m0 = blockIdx.x * 128;
    const int k0 = blockIdx.z * 64;
    if (blockIdx.y == 0)
        gemm_bf16_3t(w_ih, g_embhi, g_emblo, g_gx, 3 * H, H, m0, k0, 64);
    else
        gemm_bf16_3t(w_hh, g_h0hi, g_h0lo, g_gh, 3 * H, H, m0, k0, 64);
}
__global__ void __launch_bounds__(256, 2) k_gemm_cat(const float* __restrict__ cW) {
    gemm_bf16_3t(cW, g_cathi, g_catlo, g_cop, H, 2 * H,
                 blockIdx.x * 128, blockIdx.y * 64, 64);
}
__global__ void __launch_bounds__(256, 2) k_gemm_out(const float* __restrict__ oW,
                                                     float* __restrict__ out) {
    gemm_f16_1t(oW, g_cof, out, V, H, blockIdx.x * 128, blockIdx.y * 512, 512);
}

// ---------------- prep kernels -------------------------------------------------
__global__ void k_prep_emb(const int* __restrict__ seq, const float* __restrict__ emb) {
    int idx = blockIdx.x * 256 + threadIdx.x;   // 0..65535
    int b = idx >> 10, h = idx & 1023;
    float v = emb[(size_t)seq[b] * H + h];
    __nv_bfloat16 hi = __float2bfloat16_rn(v);
    g_embhi[idx] = hi;
    g_emblo[idx] = __float2bfloat16_rn(v - __bfloat162float(hi));
}
__global__ void k_prep_h0(const float* __restrict__ h0) {
    int idx = blockIdx.x * 256 + threadIdx.x;   // 0..65535
    float v = h0[idx];
    __nv_bfloat16 hi = __float2bfloat16_rn(v);
    g_h0hi[idx] = hi;
    g_h0lo[idx] = __float2bfloat16_rn(v - __bfloat162float(hi));
}
__global__ void k_prep_bias(const float* __restrict__ b_ih, const float* __restrict__ b_hh,
                            const float* __restrict__ cb) {
    int idx = blockIdx.x * 256 + threadIdx.x;   // 0..458751
    if (idx < 196608) {
        g_gx[idx] = b_ih[idx % 3072];
    } else if (idx < 393216) {
        int i = idx - 196608;
        g_gh[i] = b_hh[i % 3072];
    } else {
        int i = idx - 393216;
        g_cop[i] = cb[i & 1023];
    }
}
__global__ void k_prep_out(const float* __restrict__ ob, float* __restrict__ out) {
    int idx = blockIdx.x * 256 + threadIdx.x;   // 0..2047999
    out[idx] = ob[idx % V];
}

// ---------------- GRU gate fusion ---------------------------------------------
__global__ void k_gate(const float* __restrict__ h0, float* __restrict__ hid_out) {
    int idx = blockIdx.x * 256 + threadIdx.x;
    int b = idx >> 10, c = idx & 1023;
    int base = b * 3072;
    float xr = g_gx[base + c],        hr = g_gh[base + c];
    float xz = g_gx[base + 1024 + c], hz = g_gh[base + 1024 + c];
    float xn = g_gx[base + 2048 + c], hn = g_gh[base + 2048 + c];
    float r = 1.f / (1.f + __expf(-(xr + hr)));
    float z = 1.f / (1.f + __expf(-(xz + hz)));
    float n = tanhf(xn + r * hn);
    float h = (1.f - z) * n + z * h0[idx];
    g_cat[b * 2048 + c] = h;
    hid_out[idx] = h;
    __nv_bfloat16 hb = __float2bfloat16_rn(h);
    g_cathi[b * 2048 + c] = hb;
    g_catlo[b * 2048 + c] = __float2bfloat16_rn(h - __bfloat162float(hb));
}

// ---------------- one-pass attention: warp-per-timestep ------------------------
__global__ void __launch_bounds__(256, 2) k_attn(const float* __restrict__ enc) {
    __shared__ __align__(16) float s_cx[8][1024];
    __shared__ float s_m[8], s_s[8];
    const int b = blockIdx.x;
    const int c = blockIdx.y;
    const int tid  = threadIdx.x;
    const int lane = tid & 31, w = tid >> 5;

    float4 hreg[8];
#pragma unroll
    for (int i = 0; i < 8; ++i)
        hreg[i] = *reinterpret_cast<const float4*>(&g_cat[b * 2048 + 128 * i + lane * 4]);

    float4 cx[8];
#pragma unroll
    for (int i = 0; i < 8; ++i) cx[i] = make_float4(0.f, 0.f, 0.f, 0.f);
    float m = -1e30f, s = 0.f;

    const int tbase = c * 64 + w * 8;
#pragma unroll 2
    for (int it = 0; it < 8; ++it) {
        const int t = tbase + it;
        const float* ep = &enc[((size_t)t * B + b) * H];
        float4 e[8];
#pragma unroll
        for (int i = 0; i < 8; ++i)
            e[i] = *reinterpret_cast<const float4*>(&ep[128 * i + lane * 4]);

        float p = 0.f;
#pragma unroll
        for (int i = 0; i < 8; ++i)
            p += e[i].x * hreg[i].x + e[i].y * hreg[i].y + e[i].z * hreg[i].z + e[i].w * hreg[i].w;
#pragma unroll
        for (int o = 16; o > 0; o >>= 1) p += __shfl_xor_sync(0xffffffffu, p, o);

        if (lane == 0) g_scores[b * T + t] = p;

        if (p > m) {
            float al = __expf(m - p);
#pragma unroll
            for (int i = 0; i < 8; ++i) {
                cx[i].x *= al; cx[i].y *= al; cx[i].z *= al; cx[i].w *= al;
            }
            s *= al;
            m = p;
        }
        float wg = __expf(p - m);
        s += wg;
#pragma unroll
        for (int i = 0; i < 8; ++i) {
            cx[i].x += wg * e[i].x; cx[i].y += wg * e[i].y;
            cx[i].z += wg * e[i].z; cx[i].w += wg * e[i].w;
        }
    }

#pragma unroll
    for (int i = 0; i < 8; ++i)
        *reinterpret_cast<float4*>(&s_cx[w][128 * i + lane * 4]) = cx[i];
    if (lane == 0) { s_m[w] = m; s_s[w] = s; }
    __syncthreads();

    float M = s_m[0];
#pragma unroll
    for (int i = 1; i < 8; ++i) M = fmaxf(M, s_m[i]);
    float S = 0.f;
    float4 acc = make_float4(0.f, 0.f, 0.f, 0.f);
#pragma unroll
    for (int i = 0; i < 8; ++i) {
        float wt = __expf(s_m[i] - M);
        S += s_s[i] * wt;
        float4 v = *reinterpret_cast<const float4*>(&s_cx[i][tid * 4]);
        acc.x += wt * v.x; acc.y += wt * v.y; acc.z += wt * v.z; acc.w += wt * v.w;
    }
    *reinterpret_cast<float4*>(&g_pc[((size_t)b * NC + c) * H + tid * 4]) = acc;
    if (tid == 0) { g_pm[b * NC + c] = M; g_ps[b * NC + c] = S; }
}

// ---------------- attention combine -------------------------------------------
__global__ void __launch_bounds__(256) k_combine(float* __restrict__ attn_out) {
    const int b = blockIdx.x;
    const int tid = threadIdx.x;
    float pm[NC], ps[NC];
#pragma unroll
    for (int i = 0; i < NC; ++i) { pm[i] = g_pm[b * NC + i]; ps[i] = g_ps[b * NC + i]; }
    float M = pm[0];
#pragma unroll
    for (int i = 1; i < NC; ++i) M = fmaxf(M, pm[i]);
    float S = 0.f, wts[NC];
#pragma unroll
    for (int i = 0; i < NC; ++i) { wts[i] = __expf(pm[i] - M); S += ps[i] * wts[i]; }
    float invS = 1.0f / S;

    int h4 = tid * 4;
    float4 cxa = make_float4(0.f, 0.f, 0.f, 0.f);
#pragma unroll
    for (int i = 0; i < NC; ++i) {
        float4 pcv = *reinterpret_cast<const float4*>(&g_pc[((size_t)b * NC + i) * H + h4]);
        float w = wts[i];
        cxa.x += w * pcv.x; cxa.y += w * pcv.y; cxa.z += w * pcv.z; cxa.w += w * pcv.w;
    }
    cxa.x *= invS; cxa.y *= invS; cxa.z *= invS; cxa.w *= invS;
    float cv[4] = {cxa.x, cxa.y, cxa.z, cxa.w};
#pragma unroll
    for (int q = 0; q < 4; ++q) {
        int c = 1024 + h4 + q;
        __nv_bfloat16 hb = __float2bfloat16_rn(cv[q]);
        g_cathi[b * 2048 + c] = hb;
        g_catlo[b * 2048 + c] = __float2bfloat16_rn(cv[q] - __bfloat162float(hb));
    }

#pragma unroll
    for (int j = 0; j < 4; ++j) {
        int t = tid + j * 256;
        attn_out[b * T + t] = __expf(g_scores[b * T + t] - M) * invS;
    }
}

// ---------------- tanh + fp16 convert epilogue of concat GEMM ------------------
__global__ void k_tanhsplit() {
    int idx = blockIdx.x * 256 + threadIdx.x;    // 0..65535
    float v = tanhf(g_cop[idx]);
    g_cof[idx] = __float2half_rn(v);
}

// ---------------- launch ------------------------------------------------------
extern "C" void kernel_launch(void* const* d_in, const int* in_sizes, int n_in,
                              void* d_out, int out_size) {
    (void)in_sizes; (void)n_in; (void)out_size;
    const int*   seq  = (const int*)d_in[0];
    const float* h0   = (const float*)d_in[1];
    const float* enc  = (const float*)d_in[2];
    const float* emb  = (const float*)d_in[3];
    const float* w_ih = (const float*)d_in[4];
    const float* w_hh = (const float*)d_in[5];
    const float* b_ih = (const float*)d_in[6];
    const float* b_hh = (const float*)d_in[7];
    const float* cW   = (const float*)d_in[8];
    const float* cb   = (const float*)d_in[9];
    const float* oW   = (const float*)d_in[10];
    const float* ob   = (const float*)d_in[11];
    float* out = (float*)d_out;

    k_prep_emb<<<256, 256>>>(seq, emb);                         // 1
    k_prep_h0<<<256, 256>>>(h0);                                // 2
    k_prep_bias<<<1792, 256>>>(b_ih, b_hh, cb);                 // 3
    k_gemm_gru<<<dim3(24, 2, 16), 256>>>(w_ih, w_hh);           // 4  <- profiled
    k_prep_out<<<8000, 256>>>(ob, out);                         // 5
    k_gate<<<256, 256>>>(h0, out + HID_OFF);                    // 6
    k_attn<<<dim3(B, NC), 256>>>(enc);                          // 7
    k_combine<<<B, 256>>>(out + ATTN_OFF);                      // 8
    k_gemm_cat<<<dim3(8, 32), 256>>>(cW);                       // 9
    k_tanhsplit<<<256, 256>>>();                                // 10
    k_gemm_out<<<dim3(V / 128, 2), 256>>>(oW, out);             // 11
}

// round 17
// speedup vs baseline: 1.0388x; 1.0388x over previous
#include <cuda_runtime.h>
#include <cuda_bf16.h>
#include <cuda_fp16.h>
#include <cstdint>

// Problem constants
constexpr int V  = 32000;
constexpr int H  = 1024;
constexpr int B  = 64;
constexpr int T  = 1024;
constexpr int NC = 16;
constexpr int HID_OFF  = B * V;
constexpr int ATTN_OFF = HID_OFF + B * H;

// ---------------- scratch globals --------------------------------------------
__device__ float g_gx[B * 3 * H];
__device__ float g_gh[B * 3 * H];
__device__ float g_cat[B * 2 * H];
__device__ float g_scores[B * T];
__device__ float g_pm[B * NC];
__device__ float g_ps[B * NC];
__device__ float g_pc[B * NC * H];
__device__ float g_cop[B * H];

__device__ __half g_embf[B * H];            // fp16 X for GRU (input path)
__device__ __half g_h0f[B * H];             // fp16 X for GRU (hidden path)
__device__ __nv_bfloat16 g_cathi[B * 2 * H];
__device__ __nv_bfloat16 g_catlo[B * 2 * H];
__device__ __half g_cof[B * H];             // fp16 X for the out GEMM

// ---------------- helpers ------------------------------------------------------
__device__ __forceinline__ uint32_t swz(uint32_t o) { return o ^ ((o >> 3) & 0x70); }
__device__ __forceinline__ uint32_t smem_u32(const void* p) {
    uint32_t a;
    asm("{ .reg .u64 t; cvta.to.shared.u64 t, %1; cvt.u32.u64 %0, t; }" : "=r"(a) : "l"(p));
    return a;
}
__device__ __forceinline__ void ldsm4(uint32_t& r0, uint32_t& r1, uint32_t& r2, uint32_t& r3,
                                      uint32_t addr) {
    asm volatile("ldmatrix.sync.aligned.m8n8.x4.shared.b16 {%0,%1,%2,%3}, [%4];"
                 : "=r"(r0), "=r"(r1), "=r"(r2), "=r"(r3) : "r"(addr));
}
__device__ __forceinline__ void mma16816(float* c, const uint32_t* a, uint32_t b0, uint32_t b1) {
    asm volatile(
        "mma.sync.aligned.m16n8k16.row.col.f32.bf16.bf16.f32 "
        "{%0,%1,%2,%3}, {%4,%5,%6,%7}, {%8,%9}, {%0,%1,%2,%3};"
        : "+f"(c[0]), "+f"(c[1]), "+f"(c[2]), "+f"(c[3])
        : "r"(a[0]), "r"(a[1]), "r"(a[2]), "r"(a[3]), "r"(b0), "r"(b1));
}
__device__ __forceinline__ void mma16816h(float* c, const uint32_t* a, uint32_t b0, uint32_t b1) {
    asm volatile(
        "mma.sync.aligned.m16n8k16.row.col.f32.f16.f16.f32 "
        "{%0,%1,%2,%3}, {%4,%5,%6,%7}, {%8,%9}, {%0,%1,%2,%3};"
        : "+f"(c[0]), "+f"(c[1]), "+f"(c[2]), "+f"(c[3])
        : "r"(a[0]), "r"(a[1]), "r"(a[2]), "r"(a[3]), "r"(b0), "r"(b1));
}
__device__ __forceinline__ uint32_t pk2(float first, float second) {
    uint32_t r;
    asm("cvt.rn.bf16x2.f32 %0, %2, %1;" : "=r"(r) : "f"(first), "f"(second));
    return r;
}
__device__ __forceinline__ uint32_t pkh(__nv_bfloat16 a, __nv_bfloat16 b) {
    return (uint32_t)__bfloat16_as_ushort(a) | ((uint32_t)__bfloat16_as_ushort(b) << 16);
}
__device__ __forceinline__ uint32_t pk2hf(float first, float second) {
    uint32_t r;
    asm("cvt.rn.f16x2.f32 %0, %2, %1;" : "=r"(r) : "f"(first), "f"(second));
    return r;
}

// bf16 3-term layout (cat GEMM)
constexpr int OFF_WHI = 0;
constexpr int OFF_WLO = 16384;
constexpr int OFF_XHI = 32768;
constexpr int OFF_XLO = 40960;

// fp16 2-term layout (GRU GEMM): WHI 16K | WLO 16K | X 8K = 40K
constexpr int F2_WHI = 0;
constexpr int F2_WLO = 16384;
constexpr int F2_X   = 32768;

// fp16 1-term layout (out GEMM)
constexpr int F1_WHI = 0;
constexpr int F1_X   = 16384;

// ---------------- split-bf16 3-term HMMA GEMM (cat), atomic epilogue -----------
__device__ __forceinline__ void gemm_bf16_3t(const float* __restrict__ W,
                                             const __nv_bfloat16* __restrict__ Xhi,
                                             const __nv_bfloat16* __restrict__ Xlo,
                                             float* __restrict__ Cf,
                                             int NOUT, int KDIM, int m0, int k0, int kLen) {
    __shared__ __align__(1024) uint8_t sm[49152];
    const int tid = threadIdx.x;
    const int lane = tid & 31, w = tid >> 5;
    const uint32_t sb = smem_u32(sm);

    const int wr0 = tid >> 4;
    const int wkq = tid & 15;
    const float* wp = W + (size_t)(m0 + wr0) * KDIM + k0 + wkq * 4;
    const size_t wstep = (size_t)16 * KDIM;

    const int xrow  = tid >> 2;
    const int xq    = tid & 3;
    const __nv_bfloat16* xhp = Xhi + (size_t)xrow * KDIM + k0 + xq * 16;
    const __nv_bfloat16* xlp = Xlo + (size_t)xrow * KDIM + k0 + xq * 16;

    const uint32_t a_row = (w << 4) + (lane & 15);
    const uint32_t a_chi = (lane >> 4) << 4;
    const uint32_t b_row8 = (lane & 7) | (((uint32_t)lane >> 4) << 3);
    const uint32_t b_chi  = (((uint32_t)lane >> 3) & 1) << 4;

    float acc[8][4];
#pragma unroll
    for (int j = 0; j < 8; ++j)
#pragma unroll
        for (int q = 0; q < 4; ++q) acc[j][q] = 0.f;

    float4 wreg[8];
    uint4  xr[4];
#pragma unroll
    for (int q = 0; q < 8; ++q) wreg[q] = *reinterpret_cast<const float4*>(wp + q * wstep);
    xr[0] = *reinterpret_cast<const uint4*>(xhp);
    xr[1] = *reinterpret_cast<const uint4*>(xhp + 8);
    xr[2] = *reinterpret_cast<const uint4*>(xlp);
    xr[3] = *reinterpret_cast<const uint4*>(xlp + 8);

    const int nch = kLen >> 6;
    for (int ch = 0; ch < nch; ++ch) {
#pragma unroll
        for (int q = 0; q < 8; ++q) {
            float4 f = wreg[q];
            __nv_bfloat16 b0 = __float2bfloat16_rn(f.x);
            __nv_bfloat16 b1 = __float2bfloat16_rn(f.y);
            __nv_bfloat16 b2 = __float2bfloat16_rn(f.z);
            __nv_bfloat16 b3 = __float2bfloat16_rn(f.w);
            uint2 hu = make_uint2(pkh(b0, b1), pkh(b2, b3));
            uint2 lu = make_uint2(pk2(f.x - __bfloat162float(b0), f.y - __bfloat162float(b1)),
                                  pk2(f.z - __bfloat162float(b2), f.w - __bfloat162float(b3)));
            uint32_t off = swz((uint32_t)((wr0 + 16 * q) * 128 + wkq * 8));
            *reinterpret_cast<uint2*>(sm + OFF_WHI + off) = hu;
            *reinterpret_cast<uint2*>(sm + OFF_WLO + off) = lu;
        }
        {
            uint32_t o0 = swz((uint32_t)(xrow * 128 + xq * 32));
            uint32_t o1 = swz((uint32_t)(xrow * 128 + xq * 32 + 16));
            *reinterpret_cast<uint4*>(sm + OFF_XHI + o0) = xr[0];
            *reinterpret_cast<uint4*>(sm + OFF_XHI + o1) = xr[1];
            *reinterpret_cast<uint4*>(sm + OFF_XLO + o0) = xr[2];
            *reinterpret_cast<uint4*>(sm + OFF_XLO + o1) = xr[3];
        }
        __syncthreads();

        if (ch + 1 < nch) {
            const int kc = (ch + 1) * 64;
#pragma unroll
            for (int q = 0; q < 8; ++q)
                wreg[q] = *reinterpret_cast<const float4*>(wp + kc + q * wstep);
            xr[0] = *reinterpret_cast<const uint4*>(xhp + kc);
            xr[1] = *reinterpret_cast<const uint4*>(xhp + kc + 8);
            xr[2] = *reinterpret_cast<const uint4*>(xlp + kc);
            xr[3] = *reinterpret_cast<const uint4*>(xlp + kc + 8);
        }

#pragma unroll
        for (int s = 0; s < 4; ++s) {
            uint32_t ah[4], al[4];
            uint32_t aoff = swz(a_row * 128 + s * 32 + a_chi);
            ldsm4(ah[0], ah[1], ah[2], ah[3], sb + OFF_WHI + aoff);
            ldsm4(al[0], al[1], al[2], al[3], sb + OFF_WLO + aoff);
            uint32_t bh[4][4], bl[4][4];
#pragma unroll
            for (int jj = 0; jj < 4; ++jj) {
                uint32_t boff = swz((16 * jj + b_row8) * 128 + s * 32 + b_chi);
                ldsm4(bh[jj][0], bh[jj][1], bh[jj][2], bh[jj][3], sb + OFF_XHI + boff);
                ldsm4(bl[jj][0], bl[jj][1], bl[jj][2], bl[jj][3], sb + OFF_XLO + boff);
            }
#pragma unroll
            for (int jj = 0; jj < 4; ++jj) {
                mma16816(acc[2 * jj],     ah, bh[jj][0], bh[jj][1]);
                mma16816(acc[2 * jj + 1], ah, bh[jj][2], bh[jj][3]);
            }
#pragma unroll
            for (int jj = 0; jj < 4; ++jj) {
                mma16816(acc[2 * jj],     al, bh[jj][0], bh[jj][1]);
                mma16816(acc[2 * jj + 1], al, bh[jj][2], bh[jj][3]);
            }
#pragma unroll
            for (int jj = 0; jj < 4; ++jj) {
                mma16816(acc[2 * jj],     ah, bl[jj][0], bl[jj][1]);
                mma16816(acc[2 * jj + 1], ah, bl[jj][2], bl[jj][3]);
            }
        }
        __syncthreads();
    }

    const int g = lane >> 2, t = lane & 3;
    const int m = m0 + w * 16 + g;
#pragma unroll
    for (int jj = 0; jj < 8; ++jj) {
        const int b0 = 8 * jj + 2 * t;
        atomicAdd(&Cf[(size_t)b0 * NOUT + m],           acc[jj][0]);
        atomicAdd(&Cf[(size_t)(b0 + 1) * NOUT + m],     acc[jj][1]);
        atomicAdd(&Cf[(size_t)b0 * NOUT + m + 8],       acc[jj][2]);
        atomicAdd(&Cf[(size_t)(b0 + 1) * NOUT + m + 8], acc[jj][3]);
    }
}

// ---------------- split-fp16 2-term HMMA GEMM (GRU), atomic epilogue -----------
// W = Whi + Wlo (fp16 pair, ~18-bit); X single fp16.
__device__ __forceinline__ void gemm_f16_2t(const float* __restrict__ W,
                                            const __half* __restrict__ X,
                                            float* __restrict__ Cf,
                                            int NOUT, int KDIM, int m0, int k0, int kLen) {
    __shared__ __align__(1024) uint8_t sm[40960];
    const int tid = threadIdx.x;
    const int lane = tid & 31, w = tid >> 5;
    const uint32_t sb = smem_u32(sm);

    const int wr0 = tid >> 4;
    const int wkq = tid & 15;
    const float* wp = W + (size_t)(m0 + wr0) * KDIM + k0 + wkq * 4;
    const size_t wstep = (size_t)16 * KDIM;

    const int xrow  = tid >> 2;
    const int xq    = tid & 3;
    const __half* xp = X + (size_t)xrow * KDIM + k0 + xq * 16;

    const uint32_t a_row = (w << 4) + (lane & 15);
    const uint32_t a_chi = (lane >> 4) << 4;
    const uint32_t b_row8 = (lane & 7) | (((uint32_t)lane >> 4) << 3);
    const uint32_t b_chi  = (((uint32_t)lane >> 3) & 1) << 4;

    float acc[8][4];
#pragma unroll
    for (int j = 0; j < 8; ++j)
#pragma unroll
        for (int q = 0; q < 4; ++q) acc[j][q] = 0.f;

    float4 wreg[8];
    uint4  xr[2];
#pragma unroll
    for (int q = 0; q < 8; ++q) wreg[q] = *reinterpret_cast<const float4*>(wp + q * wstep);
    xr[0] = *reinterpret_cast<const uint4*>(xp);
    xr[1] = *reinterpret_cast<const uint4*>(xp + 8);

    const int nch = kLen >> 6;
    for (int ch = 0; ch < nch; ++ch) {
#pragma unroll
        for (int q = 0; q < 8; ++q) {
            float4 f = wreg[q];
            __half h0 = __float2half_rn(f.x);
            __half h1 = __float2half_rn(f.y);
            __half h2 = __float2half_rn(f.z);
            __half h3 = __float2half_rn(f.w);
            uint2 hu = make_uint2(
                (uint32_t)__half_as_ushort(h0) | ((uint32_t)__half_as_ushort(h1) << 16),
                (uint32_t)__half_as_ushort(h2) | ((uint32_t)__half_as_ushort(h3) << 16));
            uint2 lu = make_uint2(pk2hf(f.x - __half2float(h0), f.y - __half2float(h1)),
                                  pk2hf(f.z - __half2float(h2), f.w - __half2float(h3)));
            uint32_t off = swz((uint32_t)((wr0 + 16 * q) * 128 + wkq * 8));
            *reinterpret_cast<uint2*>(sm + F2_WHI + off) = hu;
            *reinterpret_cast<uint2*>(sm + F2_WLO + off) = lu;
        }
        {
            uint32_t o0 = swz((uint32_t)(xrow * 128 + xq * 32));
            uint32_t o1 = swz((uint32_t)(xrow * 128 + xq * 32 + 16));
            *reinterpret_cast<uint4*>(sm + F2_X + o0) = xr[0];
            *reinterpret_cast<uint4*>(sm + F2_X + o1) = xr[1];
        }
        __syncthreads();

        if (ch + 1 < nch) {
            const int kc = (ch + 1) * 64;
#pragma unroll
            for (int q = 0; q < 8; ++q)
                wreg[q] = *reinterpret_cast<const float4*>(wp + kc + q * wstep);
            xr[0] = *reinterpret_cast<const uint4*>(xp + kc);
            xr[1] = *reinterpret_cast<const uint4*>(xp + kc + 8);
        }

#pragma unroll
        for (int s = 0; s < 4; ++s) {
            uint32_t ah[4], al[4];
            uint32_t aoff = swz(a_row * 128 + s * 32 + a_chi);
            ldsm4(ah[0], ah[1], ah[2], ah[3], sb + F2_WHI + aoff);
            ldsm4(al[0], al[1], al[2], al[3], sb + F2_WLO + aoff);
            uint32_t bh[4][4];
#pragma unroll
            for (int jj = 0; jj < 4; ++jj) {
                uint32_t boff = swz((16 * jj + b_row8) * 128 + s * 32 + b_chi);
                ldsm4(bh[jj][0], bh[jj][1], bh[jj][2], bh[jj][3], sb + F2_X + boff);
            }
#pragma unroll
            for (int jj = 0; jj < 4; ++jj) {
                mma16816h(acc[2 * jj],     ah, bh[jj][0], bh[jj][1]);
                mma16816h(acc[2 * jj + 1], ah, bh[jj][2], bh[jj][3]);
            }
#pragma unroll
            for (int jj = 0; jj < 4; ++jj) {
                mma16816h(acc[2 * jj],     al, bh[jj][0], bh[jj][1]);
                mma16816h(acc[2 * jj + 1], al, bh[jj][2], bh[jj][3]);
            }
        }
        __syncthreads();
    }

    const int g = lane >> 2, t = lane & 3;
    const int m = m0 + w * 16 + g;
#pragma unroll
    for (int jj = 0; jj < 8; ++jj) {
        const int b0 = 8 * jj + 2 * t;
        atomicAdd(&Cf[(size_t)b0 * NOUT + m],           acc[jj][0]);
        atomicAdd(&Cf[(size_t)(b0 + 1) * NOUT + m],     acc[jj][1]);
        atomicAdd(&Cf[(size_t)b0 * NOUT + m + 8],       acc[jj][2]);
        atomicAdd(&Cf[(size_t)(b0 + 1) * NOUT + m + 8], acc[jj][3]);
    }
}

// ---------------- single-term fp16 HMMA GEMM (out projection) ------------------
__device__ __forceinline__ void gemm_f16_1t(const float* __restrict__ W,
                                            const __half* __restrict__ X,
                                            float* __restrict__ Cf,
                                            int NOUT, int KDIM, int m0, int k0, int kLen) {
    __shared__ __align__(1024) uint8_t sm[24576];
    const int tid = threadIdx.x;
    const int lane = tid & 31, w = tid >> 5;
    const uint32_t sb = smem_u32(sm);

    const int wr0 = tid >> 4;
    const int wkq = tid & 15;
    const float* wp = W + (size_t)(m0 + wr0) * KDIM + k0 + wkq * 4;
    const size_t wstep = (size_t)16 * KDIM;

    const int xrow  = tid >> 2;
    const int xq    = tid & 3;
    const __half* xp = X + (size_t)xrow * KDIM + k0 + xq * 16;

    const uint32_t a_row = (w << 4) + (lane & 15);
    const uint32_t a_chi = (lane >> 4) << 4;
    const uint32_t b_row8 = (lane & 7) | (((uint32_t)lane >> 4) << 3);
    const uint32_t b_chi  = (((uint32_t)lane >> 3) & 1) << 4;

    float acc[8][4];
#pragma unroll
    for (int j = 0; j < 8; ++j)
#pragma unroll
        for (int q = 0; q < 4; ++q) acc[j][q] = 0.f;

    float4 wreg[8];
    uint4  xr[2];
#pragma unroll
    for (int q = 0; q < 8; ++q) wreg[q] = *reinterpret_cast<const float4*>(wp + q * wstep);
    xr[0] = *reinterpret_cast<const uint4*>(xp);
    xr[1] = *reinterpret_cast<const uint4*>(xp + 8);

    const int nch = kLen >> 6;
    for (int ch = 0; ch < nch; ++ch) {
#pragma unroll
        for (int q = 0; q < 8; ++q) {
            float4 f = wreg[q];
            uint2 hu = make_uint2(pk2hf(f.x, f.y), pk2hf(f.z, f.w));
            uint32_t off = swz((uint32_t)((wr0 + 16 * q) * 128 + wkq * 8));
            *reinterpret_cast<uint2*>(sm + F1_WHI + off) = hu;
        }
        {
            uint32_t o0 = swz((uint32_t)(xrow * 128 + xq * 32));
            uint32_t o1 = swz((uint32_t)(xrow * 128 + xq * 32 + 16));
            *reinterpret_cast<uint4*>(sm + F1_X + o0) = xr[0];
            *reinterpret_cast<uint4*>(sm + F1_X + o1) = xr[1];
        }
        __syncthreads();

        if (ch + 1 < nch) {
            const int kc = (ch + 1) * 64;
#pragma unroll
            for (int q = 0; q < 8; ++q)
                wreg[q] = *reinterpret_cast<const float4*>(wp + kc + q * wstep);
            xr[0] = *reinterpret_cast<const uint4*>(xp + kc);
            xr[1] = *reinterpret_cast<const uint4*>(xp + kc + 8);
        }

#pragma unroll
        for (int s = 0; s < 4; ++s) {
            uint32_t ah[4];
            uint32_t aoff = swz(a_row * 128 + s * 32 + a_chi);
            ldsm4(ah[0], ah[1], ah[2], ah[3], sb + F1_WHI + aoff);
#pragma unroll
            for (int jj = 0; jj < 4; ++jj) {
                uint32_t boff = swz((16 * jj + b_row8) * 128 + s * 32 + b_chi);
                uint32_t bh[4];
                ldsm4(bh[0], bh[1], bh[2], bh[3], sb + F1_X + boff);
                mma16816h(acc[2 * jj],     ah, bh[0], bh[1]);
                mma16816h(acc[2 * jj + 1], ah, bh[2], bh[3]);
            }
        }
        __syncthreads();
    }

    const int g = lane >> 2, t = lane & 3;
    const int m = m0 + w * 16 + g;
#pragma unroll
    for (int jj = 0; jj < 8; ++jj) {
        const int b0 = 8 * jj + 2 * t;
        atomicAdd(&Cf[(size_t)b0 * NOUT + m],           acc[jj][0]);
        atomicAdd(&Cf[(size_t)(b0 + 1) * NOUT + m],     acc[jj][1]);
        atomicAdd(&Cf[(size_t)b0 * NOUT + m + 8],       acc[jj][2]);
        atomicAdd(&Cf[(size_t)(b0 + 1) * NOUT + m + 8], acc[jj][3]);
    }
}

__global__ void __launch_bounds__(256, 2) k_gemm_gru(const float* __restrict__ w_ih,
                                                     const float* __restrict__ w_hh) {
    const int m0 = blockIdx.x * 128;
    const int k0 = blockIdx.z * 64;
    if (blockIdx.y == 0)
        gemm_f16_2t(w_ih, g_embf, g_gx, 3 * H, H, m0, k0, 64);
    else
        gemm_f16_2t(w_hh, g_h0f, g_gh, 3 * H, H, m0, k0, 64);
}
__global__ void __launch_bounds__(256, 2) k_gemm_cat(const float* __restrict__ cW) {
    gemm_bf16_3t(cW, g_cathi, g_catlo, g_cop, H, 2 * H,
                 blockIdx.x * 128, blockIdx.y * 64, 64);
}
__global__ void __launch_bounds__(256, 2) k_gemm_out(const float* __restrict__ oW,
                                                     float* __restrict__ out) {
    gemm_f16_1t(oW, g_cof, out, V, H, blockIdx.x * 128, blockIdx.y * 512, 512);
}

// ---------------- prep kernels -------------------------------------------------
__global__ void k_prep_emb(const int* __restrict__ seq, const float* __restrict__ emb) {
    int idx = blockIdx.x * 256 + threadIdx.x;   // 0..65535
    int b = idx >> 10, h = idx & 1023;
    g_embf[idx] = __float2half_rn(emb[(size_t)seq[b] * H + h]);
}
__global__ void k_prep_h0(const float* __restrict__ h0) {
    int idx = blockIdx.x * 256 + threadIdx.x;   // 0..65535
    g_h0f[idx] = __float2half_rn(h0[idx]);
}
__global__ void k_prep_bias(const float* __restrict__ b_ih, const float* __restrict__ b_hh,
                            const float* __restrict__ cb) {
    int idx = blockIdx.x * 256 + threadIdx.x;   // 0..458751
    if (idx < 196608) {
        g_gx[idx] = b_ih[idx % 3072];
    } else if (idx < 393216) {
        int i = idx - 196608;
        g_gh[i] = b_hh[i % 3072];
    } else {
        int i = idx - 393216;
        g_cop[i] = cb[i & 1023];
    }
}
__global__ void k_prep_out(const float* __restrict__ ob, float* __restrict__ out) {
    int idx = blockIdx.x * 256 + threadIdx.x;   // 0..2047999
    out[idx] = ob[idx % V];
}

// ---------------- GRU gate fusion ---------------------------------------------
__global__ void k_gate(const float* __restrict__ h0, float* __restrict__ hid_out) {
    int idx = blockIdx.x * 256 + threadIdx.x;
    int b = idx >> 10, c = idx & 1023;
    int base = b * 3072;
    float xr = g_gx[base + c],        hr = g_gh[base + c];
    float xz = g_gx[base + 1024 + c], hz = g_gh[base + 1024 + c];
    float xn = g_gx[base + 2048 + c], hn = g_gh[base + 2048 + c];
    float r = 1.f / (1.f + __expf(-(xr + hr)));
    float z = 1.f / (1.f + __expf(-(xz + hz)));
    float n = tanhf(xn + r * hn);
    float h = (1.f - z) * n + z * h0[idx];
    g_cat[b * 2048 + c] = h;
    hid_out[idx] = h;
    __nv_bfloat16 hb = __float2bfloat16_rn(h);
    g_cathi[b * 2048 + c] = hb;
    g_catlo[b * 2048 + c] = __float2bfloat16_rn(h - __bfloat162float(hb));
}

// ---------------- one-pass attention: warp-per-timestep, streaming loads -------
__global__ void __launch_bounds__(256, 2) k_attn(const float* __restrict__ enc) {
    __shared__ __align__(16) float s_cx[8][1024];
    __shared__ float s_m[8], s_s[8];
    const int b = blockIdx.x;
    const int c = blockIdx.y;
    const int tid  = threadIdx.x;
    const int lane = tid & 31, w = tid >> 5;

    float4 hreg[8];
#pragma unroll
    for (int i = 0; i < 8; ++i)
        hreg[i] = *reinterpret_cast<const float4*>(&g_cat[b * 2048 + 128 * i + lane * 4]);

    float4 cx[8];
#pragma unroll
    for (int i = 0; i < 8; ++i) cx[i] = make_float4(0.f, 0.f, 0.f, 0.f);
    float m = -1e30f, s = 0.f;

    const int tbase = c * 64 + w * 8;
#pragma unroll 2
    for (int it = 0; it < 8; ++it) {
        const int t = tbase + it;
        const float* ep = &enc[((size_t)t * B + b) * H];
        float4 e[8];
#pragma unroll
        for (int i = 0; i < 8; ++i)
            e[i] = __ldcs(reinterpret_cast<const float4*>(&ep[128 * i + lane * 4]));

        float p = 0.f;
#pragma unroll
        for (int i = 0; i < 8; ++i)
            p += e[i].x * hreg[i].x + e[i].y * hreg[i].y + e[i].z * hreg[i].z + e[i].w * hreg[i].w;
#pragma unroll
        for (int o = 16; o > 0; o >>= 1) p += __shfl_xor_sync(0xffffffffu, p, o);

        if (lane == 0) g_scores[b * T + t] = p;

        if (p > m) {
            float al = __expf(m - p);
#pragma unroll
            for (int i = 0; i < 8; ++i) {
                cx[i].x *= al; cx[i].y *= al; cx[i].z *= al; cx[i].w *= al;
            }
            s *= al;
            m = p;
        }
        float wg = __expf(p - m);
        s += wg;
#pragma unroll
        for (int i = 0; i < 8; ++i) {
            cx[i].x += wg * e[i].x; cx[i].y += wg * e[i].y;
            cx[i].z += wg * e[i].z; cx[i].w += wg * e[i].w;
        }
    }

#pragma unroll
    for (int i = 0; i < 8; ++i)
        *reinterpret_cast<float4*>(&s_cx[w][128 * i + lane * 4]) = cx[i];
    if (lane == 0) { s_m[w] = m; s_s[w] = s; }
    __syncthreads();

    float M = s_m[0];
#pragma unroll
    for (int i = 1; i < 8; ++i) M = fmaxf(M, s_m[i]);
    float S = 0.f;
    float4 acc = make_float4(0.f, 0.f, 0.f, 0.f);
#pragma unroll
    for (int i = 0; i < 8; ++i) {
        float wt = __expf(s_m[i] - M);
        S += s_s[i] * wt;
        float4 v = *reinterpret_cast<const float4*>(&s_cx[i][tid * 4]);
        acc.x += wt * v.x; acc.y += wt * v.y; acc.z += wt * v.z; acc.w += wt * v.w;
    }
    *reinterpret_cast<float4*>(&g_pc[((size_t)b * NC + c) * H + tid * 4]) = acc;
    if (tid == 0) { g_pm[b * NC + c] = M; g_ps[b * NC + c] = S; }
}

// ---------------- attention combine -------------------------------------------
__global__ void __launch_bounds__(256) k_combine(float* __restrict__ attn_out) {
    const int b = blockIdx.x;
    const int tid = threadIdx.x;
    float pm[NC], ps[NC];
#pragma unroll
    for (int i = 0; i < NC; ++i) { pm[i] = g_pm[b * NC + i]; ps[i] = g_ps[b * NC + i]; }
    float M = pm[0];
#pragma unroll
    for (int i = 1; i < NC; ++i) M = fmaxf(M, pm[i]);
    float S = 0.f, wts[NC];
#pragma unroll
    for (int i = 0; i < NC; ++i) { wts[i] = __expf(pm[i] - M); S += ps[i] * wts[i]; }
    float invS = 1.0f / S;

    int h4 = tid * 4;
    float4 cxa = make_float4(0.f, 0.f, 0.f, 0.f);
#pragma unroll
    for (int i = 0; i < NC; ++i) {
        float4 pcv = *reinterpret_cast<const float4*>(&g_pc[((size_t)b * NC + i) * H + h4]);
        float w = wts[i];
        cxa.x += w * pcv.x; cxa.y += w * pcv.y; cxa.z += w * pcv.z; cxa.w += w * pcv.w;
    }
    cxa.x *= invS; cxa.y *= invS; cxa.z *= invS; cxa.w *= invS;
    float cv[4] = {cxa.x, cxa.y, cxa.z, cxa.w};
#pragma unroll
    for (int q = 0; q < 4; ++q) {
        int c = 1024 + h4 + q;
        __nv_bfloat16 hb = __float2bfloat16_rn(cv[q]);
        g_cathi[b * 2048 + c] = hb;
        g_catlo[b * 2048 + c] = __float2bfloat16_rn(cv[q] - __bfloat162float(hb));
    }

#pragma unroll
    for (int j = 0; j < 4; ++j) {
        int t = tid + j * 256;
        attn_out[b * T + t] = __expf(g_scores[b * T + t] - M) * invS;
    }
}

// ---------------- tanh + fp16 convert epilogue of concat GEMM ------------------
__global__ void k_tanhsplit() {
    int idx = blockIdx.x * 256 + threadIdx.x;    // 0..65535
    float v = tanhf(g_cop[idx]);
    g_cof[idx] = __float2half_rn(v);
}

// ---------------- launch ------------------------------------------------------
extern "C" void kernel_launch(void* const* d_in, const int* in_sizes, int n_in,
                              void* d_out, int out_size) {
    (void)in_sizes; (void)n_in; (void)out_size;
    const int*   seq  = (const int*)d_in[0];
    const float* h0   = (const float*)d_in[1];
    const float* enc  = (const float*)d_in[2];
    const float* emb  = (const float*)d_in[3];
    const float* w_ih = (const float*)d_in[4];
    const float* w_hh = (const float*)d_in[5];
    const float* b_ih = (const float*)d_in[6];
    const float* b_hh = (const float*)d_in[7];
    const float* cW   = (const float*)d_in[8];
    const float* cb   = (const float*)d_in[9];
    const float* oW   = (const float*)d_in[10];
    const float* ob   = (const float*)d_in[11];
    float* out = (float*)d_out;

    k_prep_emb<<<256, 256>>>(seq, emb);                         // 1
    k_prep_h0<<<256, 256>>>(h0);                                // 2
    k_prep_bias<<<1792, 256>>>(b_ih, b_hh, cb);                 // 3
    k_gemm_gru<<<dim3(24, 2, 16), 256>>>(w_ih, w_hh);           // 4  <- profiled
    k_prep_out<<<8000, 256>>>(ob, out);                         // 5
    k_gate<<<256, 256>>>(h0, out + HID_OFF);                    // 6
    k_attn<<<dim3(B, NC), 256>>>(enc);                          // 7
    k_combine<<<B, 256>>>(out + ATTN_OFF);                      // 8
    k_gemm_cat<<<dim3(8, 32), 256>>>(cW);                       // 9
    k_tanhsplit<<<256, 256>>>();                                // 10
    k_gemm_out<<<dim3(V / 128, 2), 256>>>(oW, out);             // 11
}